// round 15
// baseline (speedup 1.0000x reference)
#include <cuda_runtime.h>
#include <cstdint>

// out[i,j] = swap_mask[i,j] ? x[i, perm[i,j]] : x[i,j]
// B=16384 rows, F=2048 cols (mask is int32).
// R13 dataflow (no SMEM/barrier, predicated L1 gather, .cs on perm/mask/out,
// default policy x) reshaped for minimal CTA spread: 512-thread CTAs, one
// float4 chunk per thread -> MLP_p1=3, oe=4 (oe*MLP_p1=12 < Q_th=16, below
// the cross-CTA L1tex-queue contention knee in the B300 spread model).

#define N_FEAT   2048
#define THREADS  512

__global__ __launch_bounds__(THREADS, 4)
void swap_corruption_kernel(const float* __restrict__ x,
                            const int* __restrict__ mask,
                            const int* __restrict__ perm,
                            float* __restrict__ out)
{
    const long long base = (long long)blockIdx.x * N_FEAT;

    const float*  __restrict__ xrow = x + base;
    const float4* __restrict__ x4 = reinterpret_cast<const float4*>(xrow);
    const int4*   __restrict__ p4 = reinterpret_cast<const int4*>(perm + base);
    const int4*   __restrict__ m4 = reinterpret_cast<const int4*>(mask + base);
    float4*       __restrict__ o4 = reinterpret_cast<float4*>(out + base);

    const int v = threadIdx.x;    // 0..511: exactly one float4 per thread

    // Three independent front-batched loads per thread.
    const int4   m  = __ldcs(&m4[v]);
    const int4   p  = __ldcs(&p4[v]);
    const float4 xa = x4[v];

    // Predicated gathers: only mask-true lanes (~10%) issue the dependent LDG,
    // hitting L1/L2 on this row's freshly streamed lines.
    float4 r = xa;
    if (m.x) r.x = __ldg(&xrow[p.x]);
    if (m.y) r.y = __ldg(&xrow[p.y]);
    if (m.z) r.z = __ldg(&xrow[p.z]);
    if (m.w) r.w = __ldg(&xrow[p.w]);

    __stcs(&o4[v], r);
}

extern "C" void kernel_launch(void* const* d_in, const int* in_sizes, int n_in,
                              void* d_out, int out_size)
{
    const float* x    = (const float*)d_in[0];
    const int*   mask = (const int*)d_in[1];
    const int*   perm = (const int*)d_in[2];
    float*       out  = (float*)d_out;

    const int batch = in_sizes[0] / N_FEAT;      // 16384
    swap_corruption_kernel<<<batch, THREADS>>>(x, mask, perm, out);
}

// round 17
// speedup vs baseline: 1.0257x; 1.0257x over previous
#include <cuda_runtime.h>
#include <cstdint>

// out[i,j] = swap_mask[i,j] ? x[i, perm[i,j]] : x[i,j]
// B=16384 rows, F=2048 cols (mask is int32).
// FINAL (R13 best: 70.0us kernel, DRAM 88.4%, ~508MB = traffic floor):
//  - one CTA per row, 256 threads, 2 float4 chunks/thread (MLP_p1=6: the
//    verified optimum — 3 starves MLP, 12 spills registers)
//  - no SMEM/barrier: x is read-only, gather reads through L1 on lines the
//    CTA itself just streamed (predicated, ~10% of lanes)
//  - .cs streaming policy on perm/mask/out (zero reuse); default policy on x
//    (reused by the gather)
//  - all global traffic coalesced 16B vectors

#define N_FEAT   2048
#define THREADS  256

__global__ __launch_bounds__(THREADS, 8)
void swap_corruption_kernel(const float* __restrict__ x,
                            const int* __restrict__ mask,
                            const int* __restrict__ perm,
                            float* __restrict__ out)
{
    const long long base = (long long)blockIdx.x * N_FEAT;

    const float*  __restrict__ xrow = x + base;
    const float4* __restrict__ x4 = reinterpret_cast<const float4*>(xrow);
    const int4*   __restrict__ p4 = reinterpret_cast<const int4*>(perm + base);
    const int4*   __restrict__ m4 = reinterpret_cast<const int4*>(mask + base);
    float4*       __restrict__ o4 = reinterpret_cast<float4*>(out + base);

    const int v0 = threadIdx.x;
    const int v1 = THREADS + threadIdx.x;

    // Six independent front-batched loads (gather-dependence inputs first).
    const int4   m0 = __ldcs(&m4[v0]);
    const int4   m1 = __ldcs(&m4[v1]);
    const int4   p0 = __ldcs(&p4[v0]);
    const int4   p1 = __ldcs(&p4[v1]);
    const float4 xa = x4[v0];
    const float4 xb = x4[v1];

    // Predicated gathers: only mask-true lanes (~10%) issue the dependent LDG.
    float4 r0 = xa;
    if (m0.x) r0.x = __ldg(&xrow[p0.x]);
    if (m0.y) r0.y = __ldg(&xrow[p0.y]);
    if (m0.z) r0.z = __ldg(&xrow[p0.z]);
    if (m0.w) r0.w = __ldg(&xrow[p0.w]);

    float4 r1 = xb;
    if (m1.x) r1.x = __ldg(&xrow[p1.x]);
    if (m1.y) r1.y = __ldg(&xrow[p1.y]);
    if (m1.z) r1.z = __ldg(&xrow[p1.z]);
    if (m1.w) r1.w = __ldg(&xrow[p1.w]);

    __stcs(&o4[v0], r0);
    __stcs(&o4[v1], r1);
}

extern "C" void kernel_launch(void* const* d_in, const int* in_sizes, int n_in,
                              void* d_out, int out_size)
{
    const float* x    = (const float*)d_in[0];
    const int*   mask = (const int*)d_in[1];
    const int*   perm = (const int*)d_in[2];
    float*       out  = (float*)d_out;

    const int batch = in_sizes[0] / N_FEAT;      // 16384
    swap_corruption_kernel<<<batch, THREADS>>>(x, mask, perm, out);
}